// round 17
// baseline (speedup 1.0000x reference)
#include <cuda_runtime.h>
#include <cuda_bf16.h>
#include <stdint.h>
#include <math.h>

typedef unsigned int u32;

#define N_NODES 50000
#define N_EDGES 800000
#define F 128
#define NCLS 40

// ---------------- scratch (no allocs allowed) ----------------
__device__ float g_h[N_NODES * F];
__device__ float g_yl[N_NODES * F];
__device__ float g_yr[N_NODES * F];
__device__ int   g_rowstart[N_NODES + 1];
__device__ int   g_cursor[N_NODES];
__device__ int2  g_csr[N_EDGES];
__device__ __nv_bfloat16 g_Ah[N_NODES * F];
__device__ __nv_bfloat16 g_Al[N_NODES * F];
__device__ __nv_bfloat16 g_WhT[4 * F * F];
__device__ __nv_bfloat16 g_WlT[4 * F * F];

// ================= CSR build =================
__global__ void count_kernel(const int* __restrict__ dst, int* __restrict__ cnt) {
    int e = blockIdx.x * blockDim.x + threadIdx.x;
    if (e >= N_EDGES) return;
    int d = dst[e];
    if ((unsigned)d < N_NODES) atomicAdd(&cnt[d], 1);
}

#define SCAN_T 1024
#define SCAN_C 49
__global__ __launch_bounds__(SCAN_T) void scan_kernel(const int* __restrict__ cnt,
                                                      int* __restrict__ rowstart,
                                                      int* __restrict__ cursor) {
    __shared__ int ssum[SCAN_T];
    int t = threadIdx.x;
    int base = t * SCAN_C;
    int vals[SCAN_C];
    int local = 0;
#pragma unroll
    for (int i = 0; i < SCAN_C; i++) {
        int idx = base + i;
        vals[i] = (idx < N_NODES) ? cnt[idx] : 0;
        local += vals[i];
    }
    ssum[t] = local;
    __syncthreads();
    for (int off = 1; off < SCAN_T; off <<= 1) {
        int v = (t >= off) ? ssum[t - off] : 0;
        __syncthreads();
        ssum[t] += v;
        __syncthreads();
    }
    int run = (t > 0) ? ssum[t - 1] : 0;
#pragma unroll
    for (int i = 0; i < SCAN_C; i++) {
        int idx = base + i;
        if (idx <= N_NODES) {
            rowstart[idx] = run;
            if (idx < N_NODES) cursor[idx] = run;
        }
        run += vals[i];
    }
}

__global__ void fill_kernel(const int* __restrict__ src, const int* __restrict__ dst,
                            const float* __restrict__ ew,
                            int* __restrict__ cursor, int2* __restrict__ csr) {
    int e = blockIdx.x * blockDim.x + threadIdx.x;
    if (e >= N_EDGES) return;
    int s = src[e];
    int d = dst[e];
    if ((unsigned)s >= N_NODES || (unsigned)d >= N_NODES) return;
    int pos = atomicAdd(&cursor[d], 1);
    csr[pos] = make_int2(s, __float_as_int(ew[e]));
}

// ================= helpers =================
__device__ __forceinline__ u32 sw64(u32 byteoff) {
    return byteoff ^ ((byteoff >> 3) & 0x30u);
}

__device__ __forceinline__ u32 pack_bf16(float x, float y) {
    __nv_bfloat162 t = __floats2bfloat162_rn(x, y);
    return *reinterpret_cast<u32*>(&t);
}

__device__ __forceinline__ void ldsm4(u32& r0, u32& r1, u32& r2, u32& r3, u32 addr) {
    asm volatile("ldmatrix.sync.aligned.m8n8.x4.shared.b16 {%0,%1,%2,%3}, [%4];"
                 : "=r"(r0), "=r"(r1), "=r"(r2), "=r"(r3) : "r"(addr));
}

__device__ __forceinline__ void mma_bf16(float* c, const u32* a, const u32* b) {
    asm volatile("mma.sync.aligned.m16n8k16.row.col.f32.bf16.bf16.f32 "
                 "{%0,%1,%2,%3}, {%4,%5,%6,%7}, {%8,%9}, {%0,%1,%2,%3};"
                 : "+f"(c[0]), "+f"(c[1]), "+f"(c[2]), "+f"(c[3])
                 : "r"(a[0]), "r"(a[1]), "r"(a[2]), "r"(a[3]), "r"(b[0]), "r"(b[1]));
}

__device__ __forceinline__ void cp16(u32 smem_addr, const void* gptr, int valid16) {
    asm volatile("cp.async.cg.shared.global [%0], [%1], 16, %2;"
                 :: "r"(smem_addr), "l"(gptr), "r"(valid16) : "memory");
}

__device__ __forceinline__ void cp_commit() {
    asm volatile("cp.async.commit_group;" ::: "memory");
}

template <int N>
__device__ __forceinline__ void cp_wait() {
    asm volatile("cp.async.wait_group %0;" :: "n"(N) : "memory");
}

// ================= weight split + transpose (bf16 hi/lo, n-major) =================
__global__ void wsplit_kernel(const float* __restrict__ W0, const float* __restrict__ W1,
                              const float* __restrict__ W2, const float* __restrict__ W3,
                              __nv_bfloat16* __restrict__ whT, __nv_bfloat16* __restrict__ wlT) {
    int idx = blockIdx.x * 256 + threadIdx.x;
    int mat = blockIdx.y;
    const float* W = (mat == 0) ? W0 : ((mat == 1) ? W1 : ((mat == 2) ? W2 : W3));
    int nn = idx >> 7;
    int kk = idx & 127;
    float w = W[kk * F + nn];
    __nv_bfloat16 hv = __float2bfloat16(w);
    float hr = __bfloat162float(hv);
    whT[mat * F * F + nn * F + kk] = hv;
    wlT[mat * F * F + nn * F + kk] = __float2bfloat16(w - hr);
}

// ================= input split: fp32 X -> bf16 hi/lo =================
__global__ void asplit_kernel(const float* __restrict__ X,
                              __nv_bfloat16* __restrict__ Ah, __nv_bfloat16* __restrict__ Al) {
    int i = blockIdx.x * 256 + threadIdx.x;
    if (i >= N_NODES * F / 4) return;
    float4 v = reinterpret_cast<const float4*>(X)[i];
    float hx = __bfloat162float(__float2bfloat16(v.x));
    float hy = __bfloat162float(__float2bfloat16(v.y));
    float hz = __bfloat162float(__float2bfloat16(v.z));
    float hw = __bfloat162float(__float2bfloat16(v.w));
    uint2 hv = make_uint2(pack_bf16(v.x, v.y), pack_bf16(v.z, v.w));
    uint2 lv = make_uint2(pack_bf16(v.x - hx, v.y - hy), pack_bf16(v.z - hz, v.w - hw));
    reinterpret_cast<uint2*>(Ah)[i] = hv;
    reinterpret_cast<uint2*>(Al)[i] = lv;
}

// ================= tensor-core GEMM pair, cp.async double-buffered =================
#define STAGE_BYTES 32768
#define OF2_AH 0
#define OF2_AL 8192
#define OF2_WH 16384
#define OF2_WL 24576

__global__ __launch_bounds__(256, 2) void tc_gemm2_kernel(
    const __nv_bfloat16* __restrict__ Ah, const __nv_bfloat16* __restrict__ Al,
    const __nv_bfloat16* __restrict__ whT_all, const __nv_bfloat16* __restrict__ wlT_all,
    float* __restrict__ C0, float* __restrict__ C1,
    int mat_base, int n)
{
    extern __shared__ char smbuf[];

    float* Cout = (blockIdx.y == 0) ? C0 : C1;
    const __nv_bfloat16* WhT = whT_all + (size_t)(mat_base + blockIdx.y) * F * F;
    const __nv_bfloat16* WlT = wlT_all + (size_t)(mat_base + blockIdx.y) * F * F;

    const int tid  = threadIdx.x;
    const int lane = tid & 31;
    const int wid  = tid >> 5;
    const int wm0  = (wid & 3) * 32;
    const int wn0  = (wid >> 2) * 64;
    const int row0 = blockIdx.x * 128;

    const u32 sbase = (u32)__cvta_generic_to_shared(smbuf);

    float cacc[2][8][4];
#pragma unroll
    for (int mt = 0; mt < 2; mt++) {
#pragma unroll
        for (int nt = 0; nt < 8; nt++) {
#pragma unroll
            for (int i = 0; i < 4; i++) {
                cacc[mt][nt][i] = 0.0f;
            }
        }
    }

    auto stage = [&](int st, int ch) {
        const u32 stb = sbase + st * STAGE_BYTES;
        const int kc = ch * 32;
#pragma unroll
        for (int i = 0; i < 2; i++) {
            int u = tid + 256 * i;
            int r = u >> 2;
            int c16 = u & 3;
            u32 off = sw64((u32)(r * 64 + c16 * 16));
            int arow = row0 + r;
            int av = (arow < n) ? 16 : 0;
            const size_t aso = (size_t)((arow < n) ? arow : 0) * F + kc + c16 * 8;
            cp16(stb + OF2_AH + off, Ah + aso, av);
            cp16(stb + OF2_AL + off, Al + aso, av);
            const size_t wso = (size_t)r * F + kc + c16 * 8;
            cp16(stb + OF2_WH + off, WhT + wso, 16);
            cp16(stb + OF2_WL + off, WlT + wso, 16);
        }
        cp_commit();
    };

    auto compute = [&](int st) {
        const u32 stb = sbase + st * STAGE_BYTES;
#pragma unroll
        for (int kk = 0; kk < 32; kk += 16) {
            u32 fa_h[2][4];
            u32 fa_l[2][4];
#pragma unroll
            for (int mt = 0; mt < 2; mt++) {
                int rr = wm0 + mt * 16 + (lane & 7) + ((lane & 8) ? 8 : 0);
                int cc = kk + ((lane & 16) ? 8 : 0);
                u32 off = sw64((u32)(rr * 64 + cc * 2));
                ldsm4(fa_h[mt][0], fa_h[mt][1], fa_h[mt][2], fa_h[mt][3], stb + OF2_AH + off);
                ldsm4(fa_l[mt][0], fa_l[mt][1], fa_l[mt][2], fa_l[mt][3], stb + OF2_AL + off);
            }
#pragma unroll
            for (int q = 0; q < 4; q++) {
                int rr = wn0 + q * 16 + (lane & 7) + ((lane & 16) ? 8 : 0);
                int cc = kk + ((lane & 8) ? 8 : 0);
                u32 off = sw64((u32)(rr * 64 + cc * 2));
                u32 bh[2][2];
                u32 blo[2][2];
                u32 t0, t1, t2, t3;
                ldsm4(t0, t1, t2, t3, stb + OF2_WH + off);
                bh[0][0] = t0;
                bh[0][1] = t1;
                bh[1][0] = t2;
                bh[1][1] = t3;
                ldsm4(t0, t1, t2, t3, stb + OF2_WL + off);
                blo[0][0] = t0;
                blo[0][1] = t1;
                blo[1][0] = t2;
                blo[1][1] = t3;
#pragma unroll
                for (int mt = 0; mt < 2; mt++) {
#pragma unroll
                    for (int p = 0; p < 2; p++) {
                        int nt = q * 2 + p;
                        mma_bf16(cacc[mt][nt], fa_h[mt], bh[p]);
                        mma_bf16(cacc[mt][nt], fa_h[mt], blo[p]);
                        mma_bf16(cacc[mt][nt], fa_l[mt], bh[p]);
                    }
                }
            }
        }
    };

    stage(0, 0);
    stage(1, 1);
    cp_wait<1>();
    __syncthreads();
    compute(0);
    __syncthreads();
    stage(0, 2);
    cp_wait<1>();
    __syncthreads();
    compute(1);
    __syncthreads();
    stage(1, 3);
    cp_wait<1>();
    __syncthreads();
    compute(0);
    __syncthreads();
    cp_wait<0>();
    __syncthreads();
    compute(1);

    {
        const int cg = lane >> 2;
        const int ct = lane & 3;
#pragma unroll
        for (int mt = 0; mt < 2; mt++) {
#pragma unroll
            for (int nt = 0; nt < 8; nt++) {
                int rr = row0 + wm0 + mt * 16 + cg;
                int cc = wn0 + nt * 8 + ct * 2;
                if (rr < n) {
                    *reinterpret_cast<float2*>(&Cout[(size_t)rr * F + cc]) =
                        make_float2(cacc[mt][nt][0], cacc[mt][nt][1]);
                }
                if (rr + 8 < n) {
                    *reinterpret_cast<float2*>(&Cout[(size_t)(rr + 8) * F + cc]) =
                        make_float2(cacc[mt][nt][2], cacc[mt][nt][3]);
                }
            }
        }
    }
}

// ================= fused layer-3 GEMM pair (FFMA; small) =================
#define BK 32
#define APAD 4
__global__ __launch_bounds__(256, 2) void gemm80_kernel(
    const float* __restrict__ A,
    const float* __restrict__ W0, const float* __restrict__ W1,
    float* __restrict__ C0, float* __restrict__ C1, int n) {
    __shared__ float As[BK][128 + APAD];
    __shared__ float Ws[BK][80 + 1];

    const int row0 = blockIdx.x * 128;
    const int tid = threadIdx.x;
    const int tx = tid & 15;
    const int ty = tid >> 4;
    const int col0 = tx * 5;
    const int rowt = ty * 8;

    float acc[8][5];
#pragma unroll
    for (int j = 0; j < 8; j++) {
#pragma unroll
        for (int i = 0; i < 5; i++) {
            acc[j][i] = 0.f;
        }
    }

#pragma unroll
    for (int kc = 0; kc < F; kc += BK) {
#pragma unroll
        for (int i = 0; i < 4; i++) {
            int idx = tid + 256 * i;
            int r = idx & 127;
            int k4 = (idx >> 7) * 4;
            float4 v = make_float4(0.f, 0.f, 0.f, 0.f);
            if (row0 + r < n) {
                v = *reinterpret_cast<const float4*>(&A[(size_t)(row0 + r) * F + kc + k4]);
            }
            As[k4 + 0][r] = v.x;
            As[k4 + 1][r] = v.y;
            As[k4 + 2][r] = v.z;
            As[k4 + 3][r] = v.w;
        }
#pragma unroll
        for (int i = 0; i < 10; i++) {
            int idx = tid + 256 * i;
            int kk = idx / 80;
            int c = idx - kk * 80;
            Ws[kk][c] = (c < NCLS) ? W0[(size_t)(kc + kk) * NCLS + c]
                                   : W1[(size_t)(kc + kk) * NCLS + (c - NCLS)];
        }
        __syncthreads();

#pragma unroll 4
        for (int k = 0; k < BK; k++) {
            float a[8], w[5];
            *reinterpret_cast<float4*>(&a[0]) = *reinterpret_cast<const float4*>(&As[k][rowt]);
            *reinterpret_cast<float4*>(&a[4]) = *reinterpret_cast<const float4*>(&As[k][rowt + 4]);
#pragma unroll
            for (int i = 0; i < 5; i++) {
                w[i] = Ws[k][col0 + i];
            }
#pragma unroll
            for (int j = 0; j < 8; j++) {
#pragma unroll
                for (int i = 0; i < 5; i++) {
                    acc[j][i] += a[j] * w[i];
                }
            }
        }
        __syncthreads();
    }

    float* Cp = (tx < 8) ? C0 : C1;
    const int cbase = (tx < 8) ? col0 : (col0 - NCLS);
#pragma unroll
    for (int j = 0; j < 8; j++) {
        int row = row0 + rowt + j;
        if (row < n) {
#pragma unroll
            for (int i = 0; i < 5; i++) {
                Cp[(size_t)row * NCLS + cbase + i] = acc[j][i];
            }
        }
    }
}

// ================= gather body (per-warp edge range), unroll-8 =================
__device__ __forceinline__ float4 gather_accum(const float* __restrict__ yl,
                                               const int2* __restrict__ csr,
                                               int e0, int e1, int lane) {
    const float4* yl4 = reinterpret_cast<const float4*>(yl);
    float4 acc = make_float4(0.f, 0.f, 0.f, 0.f);
    int e = e0;
    for (; e + 8 <= e1; e += 8) {
        int2 cd[8];
#pragma unroll
        for (int j = 0; j < 8; j++) {
            cd[j] = csr[e + j];
        }
        float4 v[8];
#pragma unroll
        for (int j = 0; j < 8; j++) {
            v[j] = yl4[(size_t)cd[j].x * 32 + lane];
        }
#pragma unroll
        for (int j = 0; j < 8; j++) {
            float w = __int_as_float(cd[j].y);
            acc.x += v[j].x * w;
            acc.y += v[j].y * w;
            acc.z += v[j].z * w;
            acc.w += v[j].w * w;
        }
    }
    for (; e + 2 <= e1; e += 2) {
        int2 c0 = csr[e];
        int2 c1 = csr[e + 1];
        float4 v0 = yl4[(size_t)c0.x * 32 + lane];
        float4 v1 = yl4[(size_t)c1.x * 32 + lane];
        float w0 = __int_as_float(c0.y);
        float w1 = __int_as_float(c1.y);
        acc.x += v0.x * w0 + v1.x * w1;
        acc.y += v0.y * w0 + v1.y * w1;
        acc.z += v0.z * w0 + v1.z * w1;
        acc.w += v0.w * w0 + v1.w * w1;
    }
    if (e < e1) {
        int2 c0 = csr[e];
        float w0 = __int_as_float(c0.y);
        float4 v0 = yl4[(size_t)c0.x * 32 + lane];
        acc.x += v0.x * w0;
        acc.y += v0.y * w0;
        acc.z += v0.z * w0;
        acc.w += v0.w * w0;
    }
    return acc;
}

// ================= gather128: 2 warps per node, smem combine =================
// block 256 = 4 nodes x 2 warps. 50000 % 4 == 0 -> no partial blocks.
__device__ __forceinline__ float4 gather128_node(const float* __restrict__ yl,
                                                 const int* __restrict__ rowstart,
                                                 const int2* __restrict__ csr,
                                                 float4* __restrict__ comb,
                                                 int node, int sub, int lane, int nib) {
    int e0 = rowstart[node];
    int e1 = rowstart[node + 1];
    int mid = e0 + ((e1 - e0 + 1) >> 1);
    int a0 = sub ? mid : e0;
    int a1 = sub ? e1 : mid;

    float4 acc = gather_accum(yl, csr, a0, a1, lane);

    if (sub == 1) {
        comb[nib * 32 + lane] = acc;
    }
    __syncthreads();
    if (sub == 0) {
        float4 o2 = comb[nib * 32 + lane];
        acc.x += o2.x;
        acc.y += o2.y;
        acc.z += o2.z;
        acc.w += o2.w;
    }
    return acc;
}

__global__ __launch_bounds__(256) void gather128_bf16_kernel(
    const float* __restrict__ yl, const float* __restrict__ yr,
    const float* __restrict__ bl,
    const int* __restrict__ rowstart, const int2* __restrict__ csr,
    __nv_bfloat16* __restrict__ outh, __nv_bfloat16* __restrict__ outl) {
    __shared__ float4 comb[4 * 32];
    int gtid = blockIdx.x * blockDim.x + threadIdx.x;
    int node = gtid >> 6;
    int sub  = (gtid >> 5) & 1;
    int lane = gtid & 31;
    int nib  = (threadIdx.x >> 6);

    float4 acc = gather128_node(yl, rowstart, csr, comb, node, sub, lane, nib);
    if (sub != 0) return;

    int deg = rowstart[node + 1] - rowstart[node];
    float inv = 1.0f / fmaxf((float)deg, 1.0f);
    float4 selfv = reinterpret_cast<const float4*>(yr)[(size_t)node * 32 + lane];
    float4 biasv = reinterpret_cast<const float4*>(bl)[lane];
    float4 o;
    o.x = fmaxf(acc.x * inv + selfv.x + biasv.x, 0.f);
    o.y = fmaxf(acc.y * inv + selfv.y + biasv.y, 0.f);
    o.z = fmaxf(acc.z * inv + selfv.z + biasv.z, 0.f);
    o.w = fmaxf(acc.w * inv + selfv.w + biasv.w, 0.f);

    float hx = __bfloat162float(__float2bfloat16(o.x));
    float hy = __bfloat162float(__float2bfloat16(o.y));
    float hz = __bfloat162float(__float2bfloat16(o.z));
    float hw = __bfloat162float(__float2bfloat16(o.w));
    uint2 hv = make_uint2(pack_bf16(o.x, o.y), pack_bf16(o.z, o.w));
    uint2 lv = make_uint2(pack_bf16(o.x - hx, o.y - hy), pack_bf16(o.z - hz, o.w - hw));
    reinterpret_cast<uint2*>(outh)[(size_t)node * 32 + lane] = hv;
    reinterpret_cast<uint2*>(outl)[(size_t)node * 32 + lane] = lv;
}

__global__ __launch_bounds__(256) void gather128_f32_kernel(
    const float* __restrict__ yl, const float* __restrict__ yr,
    const float* __restrict__ bl,
    const int* __restrict__ rowstart, const int2* __restrict__ csr,
    float* __restrict__ out) {
    __shared__ float4 comb[4 * 32];
    int gtid = blockIdx.x * blockDim.x + threadIdx.x;
    int node = gtid >> 6;
    int sub  = (gtid >> 5) & 1;
    int lane = gtid & 31;
    int nib  = (threadIdx.x >> 6);

    float4 acc = gather128_node(yl, rowstart, csr, comb, node, sub, lane, nib);
    if (sub != 0) return;

    int deg = rowstart[node + 1] - rowstart[node];
    float inv = 1.0f / fmaxf((float)deg, 1.0f);
    float4 selfv = reinterpret_cast<const float4*>(yr)[(size_t)node * 32 + lane];
    float4 biasv = reinterpret_cast<const float4*>(bl)[lane];
    float4 o;
    o.x = fmaxf(acc.x * inv + selfv.x + biasv.x, 0.f);
    o.y = fmaxf(acc.y * inv + selfv.y + biasv.y, 0.f);
    o.z = fmaxf(acc.z * inv + selfv.z + biasv.z, 0.f);
    o.w = fmaxf(acc.w * inv + selfv.w + biasv.w, 0.f);
    reinterpret_cast<float4*>(out)[(size_t)node * 32 + lane] = o;
}

// ================= gather40 + log_softmax: 2 warps per node, smem combine =================
__global__ __launch_bounds__(256) void gather40_ls_kernel(
    const float* __restrict__ yl, const float* __restrict__ yr,
    const float* __restrict__ bl,
    const int* __restrict__ rowstart, const int2* __restrict__ csr,
    float* __restrict__ out) {
    __shared__ float comb0[4 * 32];
    __shared__ float comb1[4 * 8];
    int gtid = blockIdx.x * blockDim.x + threadIdx.x;
    int node = gtid >> 6;
    int sub  = (gtid >> 5) & 1;
    int lane = gtid & 31;
    int nib  = (threadIdx.x >> 6);

    int e0 = rowstart[node];
    int e1 = rowstart[node + 1];
    int mid = e0 + ((e1 - e0 + 1) >> 1);
    int a0 = sub ? mid : e0;
    int a1 = sub ? e1 : mid;

    float acc0 = 0.f;
    float acc1 = 0.f;
    const bool hi = (lane < NCLS - 32);

    int e = a0;
    for (; e + 4 <= a1; e += 4) {
        int2 cd[4];
#pragma unroll
        for (int j = 0; j < 4; j++) {
            cd[j] = csr[e + j];
        }
        float v0[4];
        float v1[4];
#pragma unroll
        for (int j = 0; j < 4; j++) {
            size_t sb = (size_t)cd[j].x * NCLS;
            v0[j] = yl[sb + lane];
            v1[j] = hi ? yl[sb + 32 + lane] : 0.f;
        }
#pragma unroll
        for (int j = 0; j < 4; j++) {
            float w = __int_as_float(cd[j].y);
            acc0 += v0[j] * w;
            acc1 += v1[j] * w;
        }
    }
    for (; e < a1; e++) {
        int2 c0 = csr[e];
        float w0 = __int_as_float(c0.y);
        size_t sb0 = (size_t)c0.x * NCLS;
        acc0 += yl[sb0 + lane] * w0;
        if (hi) {
            acc1 += yl[sb0 + 32 + lane] * w0;
        }
    }

    if (sub == 1) {
        comb0[nib * 32 + lane] = acc0;
        if (hi) {
            comb1[nib * 8 + lane] = acc1;
        }
    }
    __syncthreads();
    if (sub != 0) return;
    acc0 += comb0[nib * 32 + lane];
    if (hi) {
        acc1 += comb1[nib * 8 + lane];
    }

    float inv = 1.0f / fmaxf((float)(e1 - e0), 1.0f);
    size_t base = (size_t)node * NCLS;
    float za = acc0 * inv + yr[base + lane] + bl[lane];
    float zb = hi ? (acc1 * inv + yr[base + 32 + lane] + bl[32 + lane]) : -INFINITY;

    float m = fmaxf(za, zb);
#pragma unroll
    for (int off = 16; off > 0; off >>= 1) {
        m = fmaxf(m, __shfl_xor_sync(0xFFFFFFFF, m, off));
    }

    float s = __expf(za - m) + (hi ? __expf(zb - m) : 0.f);
#pragma unroll
    for (int off = 16; off > 0; off >>= 1) {
        s += __shfl_xor_sync(0xFFFFFFFF, s, off);
    }

    float ls = m + __logf(s);
    out[base + lane] = za - ls;
    if (hi) {
        out[base + 32 + lane] = zb - ls;
    }
}

// ================= host launcher =================
extern "C" void kernel_launch(void* const* d_in, const int* in_sizes, int n_in,
                              void* d_out, int out_size) {
    const float* x   = (const float*)d_in[0];
    const int* ei    = (const int*)d_in[1];
    const float* ew  = (const float*)d_in[2];
    const float* Wl1 = (const float*)d_in[3];
    const float* bl1 = (const float*)d_in[4];
    const float* Wr1 = (const float*)d_in[5];
    const float* Wl2 = (const float*)d_in[6];
    const float* bl2 = (const float*)d_in[7];
    const float* Wr2 = (const float*)d_in[8];
    const float* Wl3 = (const float*)d_in[9];
    const float* bl3 = (const float*)d_in[10];
    const float* Wr3 = (const float*)d_in[11];
    float* out = (float*)d_out;

    const int* src = ei;
    const int* dst = ei + N_EDGES;

    float *p_h, *p_yl, *p_yr;
    int *p_rowstart, *p_cursor;
    int2 *p_csr;
    __nv_bfloat16 *p_whT, *p_wlT, *p_Ah, *p_Al;
    cudaGetSymbolAddress((void**)&p_h, g_h);
    cudaGetSymbolAddress((void**)&p_yl, g_yl);
    cudaGetSymbolAddress((void**)&p_yr, g_yr);
    cudaGetSymbolAddress((void**)&p_rowstart, g_rowstart);
    cudaGetSymbolAddress((void**)&p_cursor, g_cursor);
    cudaGetSymbolAddress((void**)&p_csr, g_csr);
    cudaGetSymbolAddress((void**)&p_whT, g_WhT);
    cudaGetSymbolAddress((void**)&p_wlT, g_WlT);
    cudaGetSymbolAddress((void**)&p_Ah, g_Ah);
    cudaGetSymbolAddress((void**)&p_Al, g_Al);

    cudaFuncSetAttribute(tc_gemm2_kernel, cudaFuncAttributeMaxDynamicSharedMemorySize, 65536);

    const int EB = (N_EDGES + 255) / 256;
    const dim3 TC_GRID((N_NODES + 127) / 128, 2);
    const int GEMM80_GRID = (N_NODES + 127) / 128;
    const int GATHER_BLOCKS2 = (N_NODES * 64) / 256;     // 2 warps per node
    const int ASPLIT_BLOCKS = (N_NODES * F / 4 + 255) / 256;

    cudaMemsetAsync(p_cursor, 0, N_NODES * sizeof(int));
    count_kernel<<<EB, 256>>>(dst, p_cursor);
    wsplit_kernel<<<dim3(64, 4), 256>>>(Wl1, Wr1, Wl2, Wr2, p_whT, p_wlT);
    asplit_kernel<<<ASPLIT_BLOCKS, 256>>>(x, p_Ah, p_Al);

    // ---- layer 1 GEMM (ncu capture slot) ----
    tc_gemm2_kernel<<<TC_GRID, 256, 65536>>>(p_Ah, p_Al, p_whT, p_wlT, p_yl, p_yr, 0, N_NODES);

    // ---- CSR finish ----
    scan_kernel<<<1, SCAN_T>>>(p_cursor, p_rowstart, p_cursor);
    fill_kernel<<<EB, 256>>>(src, dst, ew, p_cursor, p_csr);

    // ---- layer 1 gather ----
    gather128_bf16_kernel<<<GATHER_BLOCKS2, 256>>>(p_yl, p_yr, bl1, p_rowstart, p_csr, p_Ah, p_Al);

    // ---- layer 2 ----
    tc_gemm2_kernel<<<TC_GRID, 256, 65536>>>(p_Ah, p_Al, p_whT, p_wlT, p_yl, p_yr, 2, N_NODES);
    gather128_f32_kernel<<<GATHER_BLOCKS2, 256>>>(p_yl, p_yr, bl2, p_rowstart, p_csr, p_h);

    // ---- layer 3 ----
    gemm80_kernel<<<GEMM80_GRID, 256>>>(p_h, Wl3, Wr3, p_yl, p_yr, N_NODES);
    gather40_ls_kernel<<<GATHER_BLOCKS2, 256>>>(p_yl, p_yr, bl3, p_rowstart, p_csr, out);
}